// round 7
// baseline (speedup 1.0000x reference)
#include <cuda_runtime.h>
#include <cstdint>

// ---------------------------------------------------------------------------
// SRNN forward:
//   inp_cur[t,b,r] = sum_i x[b,i,t] * w_inp[r,i]
//   per step t=0..998:
//     v1 = ALPHA*v + z @ w_rec_eff.T + inp_cur[t] - z*THR   (w_rec diag zeroed)
//     z1 = (v1 > THR);  vo1 = KAPPA*vo + z1 @ w_out.T
//   out[0]=0, out[t+1]=vo1.  out shape (1000,128,32) f32
// ---------------------------------------------------------------------------

#define N_B      128
#define INP_DIM  256
#define N_T      1000
#define N_REC    512
#define OUT_DIM  32
#define N_STEPS  999

#define ALPHA 0.9512294245007140f
#define KAPPA 0.9512294245007140f
#define THR   0.6f

#define ROWS  (N_STEPS * N_B)      // 127872 = 864 * 148
#define ROWS_PER_CTA 864

#define WSTEPS 16
#define NWIN   63                  // ceil(999/16); last window has 7 steps

// ---- scratch (__device__ globals; no allocation) ----
// g_inp padded by one window so the last cp.async window never reads OOB.
__device__ float    g_inp[(size_t)N_B * N_STEPS * N_REC + WSTEPS * N_REC];
__device__ unsigned g_masks[(size_t)ROWS * 8];              // 256-bit mask per (t,b)
__device__ float    g_wrecT[N_REC * N_REC];                 // [s][r], diag 0
__device__ float    g_woutT[N_REC * OUT_DIM];               // [r][o]
__device__ float    g_winpT[INP_DIM * N_REC];               // [i][r]

// ---------------------------------------------------------------------------
// Kernel 1: pack x (b,i,t) into per-(t,b) 256-bit masks. Coalesced over t.
// ---------------------------------------------------------------------------
__global__ void k_masks(const float* __restrict__ x) {
    int b = blockIdx.x;
    int t = blockIdx.y * 256 + threadIdx.x;
    if (t >= N_STEPS) return;

    unsigned m[8] = {0,0,0,0,0,0,0,0};
    const float* xp = x + (size_t)b * INP_DIM * N_T + t;
#pragma unroll
    for (int i = 0; i < INP_DIM; i++) {
        if (xp[(size_t)i * N_T] > 0.5f) m[i >> 5] |= (1u << (i & 31));
    }
    unsigned* dst = g_masks + ((size_t)t * N_B + b) * 8;
#pragma unroll
    for (int w = 0; w < 8; w++) dst[w] = m[w];
}

// ---------------------------------------------------------------------------
// Kernel 2: weight transposes.
// ---------------------------------------------------------------------------
__global__ void k_prep(const float* __restrict__ w_rec,
                       const float* __restrict__ w_out,
                       const float* __restrict__ w_inp) {
    int stride = gridDim.x * blockDim.x;
    int idx0 = blockIdx.x * blockDim.x + threadIdx.x;

    for (int i = idx0; i < N_REC * N_REC; i += stride) {
        int s = i >> 9, r = i & (N_REC - 1);
        float v = w_rec[(size_t)r * N_REC + s];
        g_wrecT[i] = (r == s) ? 0.0f : v;
    }
    for (int i = idx0; i < N_REC * OUT_DIM; i += stride) {
        int r = i >> 5, o = i & 31;
        g_woutT[i] = w_out[(size_t)o * N_REC + r];
    }
    for (int i = idx0; i < INP_DIM * N_REC; i += stride) {
        int ii = i >> 9, r = i & (N_REC - 1);
        g_winpT[i] = w_inp[(size_t)r * INP_DIM + ii];
    }
}

// ---------------------------------------------------------------------------
// Kernel 3: sparse input GEMM — warp-per-TWO-rows, prefetched mask loads,
// two independent ffs->LDS.128->FADD chains interleaved for ILP.
//   grid (4 rec-slices, 148 chunks), 256 threads (8 warps).
//   Smem: w_inpT slice [256 i][128 r] fp32 (128 KB).
// ---------------------------------------------------------------------------
#define K_INP_SMEM (INP_DIM * 128 * 4)   // 128 KB

__global__ void __launch_bounds__(256) k_inp_kernel() {
    extern __shared__ float w_sh[];               // [256 i][128 r]

    int slice = blockIdx.x;                       // 0..3
    int chunk = blockIdx.y;                       // 0..147
    int tid   = threadIdx.x;
    int wid   = tid >> 5;
    int lane  = tid & 31;
    int r0    = slice * 128;
    int loff  = lane << 2;

    for (int idx = tid; idx < INP_DIM * 128; idx += 256) {
        int i = idx >> 7, rr = idx & 127;
        w_sh[idx] = g_winpT[(size_t)i * N_REC + r0 + rr];
    }
    __syncthreads();

    int rowbase = chunk * ROWS_PER_CTA;

    // lanes 0..7 carry rowA's 8 mask words, lanes 8..15 carry rowB's
    auto load_masks = [&](int pairbase) -> unsigned {
        unsigned mw = 0;
        if (lane < 16) {
            int row = pairbase + ((lane >> 3) << 3) + wid;   // +0 or +8
            mw = __ldg(&g_masks[(size_t)row * 8 + (lane & 7)]);
        }
        return mw;
    };

    unsigned mw = load_masks(rowbase);

    for (int j2 = 0; j2 < ROWS_PER_CTA / 16; j2++) {         // 54 pairs
        int pairbase = rowbase + j2 * 16;
        unsigned cur = mw;
        if (j2 < ROWS_PER_CTA / 16 - 1)
            mw = load_masks(pairbase + 16);

        float4 aA = make_float4(0.f, 0.f, 0.f, 0.f);
        float4 aB = make_float4(0.f, 0.f, 0.f, 0.f);
#pragma unroll
        for (int wd = 0; wd < 8; wd++) {
            unsigned mA = __shfl_sync(0xffffffffu, cur, wd);
            unsigned mB = __shfl_sync(0xffffffffu, cur, 8 + wd);
            int ibase = wd * 32;
            while (mA | mB) {
                if (mA) {
                    int i = ibase + __ffs((int)mA) - 1;
                    mA &= (mA - 1);
                    float4 wv = *(const float4*)&w_sh[(i << 7) + loff];
                    aA.x += wv.x; aA.y += wv.y; aA.z += wv.z; aA.w += wv.w;
                }
                if (mB) {
                    int i = ibase + __ffs((int)mB) - 1;
                    mB &= (mB - 1);
                    float4 wv = *(const float4*)&w_sh[(i << 7) + loff];
                    aB.x += wv.x; aB.y += wv.y; aB.z += wv.z; aB.w += wv.w;
                }
            }
        }
        int rowA = pairbase + wid, rowB = pairbase + 8 + wid;
        int tA = rowA >> 7, bA = rowA & 127;
        int tB = rowB >> 7, bB = rowB & 127;
        *((float4*)(g_inp + ((size_t)bA * N_STEPS + tA) * N_REC + r0) + lane) = aA;
        *((float4*)(g_inp + ((size_t)bB * N_STEPS + tB) * N_REC + r0) + lane) = aB;
    }
}

// ---------------------------------------------------------------------------
// Kernel 4: speculative scan with cp.async double-buffered smem windows.
//   1 CTA/batch, 512 threads (neuron/thread). Fixed 16-step windows; events
//   handled inside the window with extra reduce rounds (~9 per batch total).
//   Window buffers (2 x 32 KB) in DYNAMIC shared memory (static cap is 48 KB).
// ---------------------------------------------------------------------------
#define K_SCAN_SMEM (2 * WSTEPS * N_REC * 4)     // 65536 bytes

__device__ __forceinline__ float gather_rec(const volatile unsigned* mask, int r) {
    float acc = 0.f;
#pragma unroll 4
    for (int wd = 0; wd < 16; wd++) {
        unsigned m = mask[wd];
        while (m) {
            int l = __ffs((int)m) - 1;
            m &= (m - 1);
            int s = (wd << 5) + l;
            acc += g_wrecT[((size_t)s << 9) + r];
        }
    }
    return acc;
}

__device__ __forceinline__ float gather_out(const volatile unsigned* mask, int o) {
    float acc = 0.f;
#pragma unroll 4
    for (int wd = 0; wd < 16; wd++) {
        unsigned m = mask[wd];
        while (m) {
            int l = __ffs((int)m) - 1;
            m &= (m - 1);
            int s = (wd << 5) + l;
            acc += g_woutT[(s << 5) + o];
        }
    }
    return acc;
}

__global__ void __launch_bounds__(512) k_scan(float* __restrict__ out) {
    extern __shared__ float sbuf[];                // [2][WSTEPS*N_REC], 64 KB dynamic
    __shared__ unsigned smaskS[2][16];             // spike identity (ping-pong)
    __shared__ unsigned sorS[2][16];               // per-warp spike-bit OR

    int b    = blockIdx.x;
    int tid  = threadIdx.x;
    int wid  = tid >> 5;
    int lane = tid & 31;

    const float* gbase = g_inp + (size_t)b * N_STEPS * N_REC;

    // one window = 32 KB contiguous; 512 threads x 4 x 16B cp.async
    auto issue_copy = [&](int w, int buf) {
        const float* src = gbase + (size_t)w * WSTEPS * N_REC + tid * 4;
        unsigned dst = (unsigned)__cvta_generic_to_shared(
            &sbuf[buf * (WSTEPS * N_REC) + tid * 4]);
#pragma unroll
        for (int j = 0; j < 4; j++)
            asm volatile("cp.async.cg.shared.global [%0], [%1], 16;" ::
                         "r"(dst + j * 8192), "l"(src + j * 2048) : "memory");
        asm volatile("cp.async.commit_group;" ::: "memory");
    };

    if (tid < OUT_DIM) out[b * OUT_DIM + tid] = 0.f;       // out[0] = 0

    issue_copy(0, 0);
    issue_copy(1, 1);

    float v = 0.f, zprev = 0.f, vo = 0.f;
    int prev_any = 0, pm = 0, q = 0;

    for (int w = 0; w < NWIN; w++) {
        int t0 = w * WSTEPS;
        int C = N_STEPS - t0; if (C > WSTEPS) C = WSTEPS;

        asm volatile("cp.async.wait_group 1;" ::: "memory");
        __syncthreads();
        const float* sb = sbuf + (w & 1) * (WSTEPS * N_REC);

        int c0 = 0;
        while (c0 < C) {
            // speculative pass from c0: own-spike dynamics only
            float v_s = v, z_s = zprev;
            unsigned bits = 0;
            for (int c = c0; c < C; c++) {
                float vn = fmaf(ALPHA, v_s, sb[c * N_REC + tid]) - z_s * THR;
                if (c == c0 && prev_any) vn += gather_rec(smaskS[pm], tid);
                int z = vn > THR;
                bits |= (unsigned)z << c;
                v_s = vn; z_s = z ? 1.f : 0.f;
            }
            unsigned wor = __reduce_or_sync(0xffffffffu, bits);
            if (lane == 0) sorS[q][wid] = wor;
            __syncthreads();
            unsigned allbits = 0;
#pragma unroll
            for (int k = 0; k < 16; k++) allbits |= sorS[q][k];
            q ^= 1;

            if (!allbits) {
                // no spikes in [c0, C) anywhere -> commit; vo pure decay (exact)
                v = v_s; zprev = 0.f;
                if (wid == 0) {
                    for (int c = c0; c < C; c++) {
                        vo = KAPPA * vo;
                        out[(size_t)(t0 + c + 1) * (N_B * OUT_DIM) + b * OUT_DIM + lane] = vo;
                    }
                }
                prev_any = 0;
                c0 = C;
            } else {
                int cs = __ffs((int)allbits) - 1;          // earliest spike step >= c0
                int myz = (bits >> cs) & 1;
                unsigned bal = __ballot_sync(0xffffffffu, myz);
                int np = pm ^ 1;
                if (lane == 0) smaskS[np][wid] = bal;
                __syncthreads();

                // replay c0..cs (no foreign spikes before cs -> exact)
                float vr = v, zr = zprev;
                for (int c = c0; c <= cs; c++) {
                    float vn = fmaf(ALPHA, vr, sb[c * N_REC + tid]) - zr * THR;
                    if (c == c0 && prev_any) vn += gather_rec(smaskS[pm], tid);
                    int z = vn > THR;
                    vr = vn; zr = z ? 1.f : 0.f;
                }
                v = vr; zprev = zr;

                if (wid == 0) {
                    for (int c = c0; c < cs; c++) {
                        vo = KAPPA * vo;
                        out[(size_t)(t0 + c + 1) * (N_B * OUT_DIM) + b * OUT_DIM + lane] = vo;
                    }
                    vo = KAPPA * vo + gather_out(smaskS[np], lane);
                    out[(size_t)(t0 + cs + 1) * (N_B * OUT_DIM) + b * OUT_DIM + lane] = vo;
                }
                prev_any = 1; pm = np;
                c0 = cs + 1;
            }
        }

        __syncthreads();                 // everyone done reading sbuf[w&1]
        int wn = w + 2; if (wn > NWIN - 1) wn = NWIN - 1;   // clamped (pad covers tail)
        issue_copy(wn, w & 1);
    }
    asm volatile("cp.async.wait_all;" ::: "memory");
}

// ---------------------------------------------------------------------------
extern "C" void kernel_launch(void* const* d_in, const int* in_sizes, int n_in,
                              void* d_out, int out_size) {
    const float* x     = (const float*)d_in[0];
    const float* w_inp = (const float*)d_in[1];
    const float* w_rec = (const float*)d_in[2];
    const float* w_out = (const float*)d_in[3];
    float* out = (float*)d_out;

    cudaFuncSetAttribute(k_inp_kernel,
                         cudaFuncAttributeMaxDynamicSharedMemorySize, K_INP_SMEM);
    cudaFuncSetAttribute(k_scan,
                         cudaFuncAttributeMaxDynamicSharedMemorySize, K_SCAN_SMEM);

    k_masks<<<dim3(N_B, 4), 256>>>(x);
    k_prep<<<256, 256>>>(w_rec, w_out, w_inp);
    k_inp_kernel<<<dim3(4, 148), 256, K_INP_SMEM>>>();
    k_scan<<<N_B, 512, K_SCAN_SMEM>>>(out);
}

// round 8
// speedup vs baseline: 1.5716x; 1.5716x over previous
#include <cuda_runtime.h>
#include <cstdint>

// ---------------------------------------------------------------------------
// SRNN forward:
//   inp_cur[t,b,r] = sum_i x[b,i,t] * w_inp[r,i]
//   per step t=0..998:
//     v1 = ALPHA*v + z @ w_rec_eff.T + inp_cur[t] - z*THR   (w_rec diag zeroed)
//     z1 = (v1 > THR);  vo1 = KAPPA*vo + z1 @ w_out.T
//   out[0]=0, out[t+1]=vo1.  out shape (1000,128,32) f32
// ---------------------------------------------------------------------------

#define N_B      128
#define INP_DIM  256
#define N_T      1000
#define N_REC    512
#define OUT_DIM  32
#define N_STEPS  999

#define ALPHA 0.9512294245007140f
#define KAPPA 0.9512294245007140f
#define THR   0.6f

#define ROWS  (N_STEPS * N_B)      // 127872 = 864 * 148
#define ROWS_PER_CTA 864

#define WSTEPS 16
#define NWIN   63                  // ceil(999/16); last window has 7 steps

// ---- scratch (__device__ globals; no allocation) ----
// g_inp padded by one window so the last cp.async window never reads OOB.
__device__ float    g_inp[(size_t)N_B * N_STEPS * N_REC + WSTEPS * N_REC];
__device__ unsigned g_masks[(size_t)ROWS * 8];              // 256-bit mask per (t,b)
__device__ float    g_wrecT[N_REC * N_REC];                 // [s][r], diag 0
__device__ float    g_woutT[N_REC * OUT_DIM];               // [r][o]
__device__ float    g_winpT[INP_DIM * N_REC];               // [i][r]

// ---------------------------------------------------------------------------
// Kernel 1: pack x (b,i,t) into per-(t,b) 256-bit masks. Coalesced over t.
// ---------------------------------------------------------------------------
__global__ void k_masks(const float* __restrict__ x) {
    int b = blockIdx.x;
    int t = blockIdx.y * 256 + threadIdx.x;
    if (t >= N_STEPS) return;

    unsigned m[8] = {0,0,0,0,0,0,0,0};
    const float* xp = x + (size_t)b * INP_DIM * N_T + t;
#pragma unroll
    for (int i = 0; i < INP_DIM; i++) {
        if (xp[(size_t)i * N_T] > 0.5f) m[i >> 5] |= (1u << (i & 31));
    }
    unsigned* dst = g_masks + ((size_t)t * N_B + b) * 8;
#pragma unroll
    for (int w = 0; w < 8; w++) dst[w] = m[w];
}

// ---------------------------------------------------------------------------
// Kernel 2: weight transposes.
// ---------------------------------------------------------------------------
__global__ void k_prep(const float* __restrict__ w_rec,
                       const float* __restrict__ w_out,
                       const float* __restrict__ w_inp) {
    int stride = gridDim.x * blockDim.x;
    int idx0 = blockIdx.x * blockDim.x + threadIdx.x;

    for (int i = idx0; i < N_REC * N_REC; i += stride) {
        int s = i >> 9, r = i & (N_REC - 1);
        float v = w_rec[(size_t)r * N_REC + s];
        g_wrecT[i] = (r == s) ? 0.0f : v;
    }
    for (int i = idx0; i < N_REC * OUT_DIM; i += stride) {
        int r = i >> 5, o = i & 31;
        g_woutT[i] = w_out[(size_t)o * N_REC + r];
    }
    for (int i = idx0; i < INP_DIM * N_REC; i += stride) {
        int ii = i >> 9, r = i & (N_REC - 1);
        g_winpT[i] = w_inp[(size_t)r * INP_DIM + ii];
    }
}

// ---------------------------------------------------------------------------
// Kernel 3: sparse input GEMM — EXACT R2 version (wall-clock-anchored ~650us).
//   warp-per-row, prefetched 32B mask loads, ffs->LDS.128->FADD.
//   grid (4 rec-slices, 148 chunks), 256 threads (8 warps), 128 KB smem.
// ---------------------------------------------------------------------------
#define K_INP_SMEM (INP_DIM * 128 * 4)

__global__ void __launch_bounds__(256) k_inp_kernel() {
    extern __shared__ float w_sh[];               // [256 i][128 r]

    int slice = blockIdx.x;                       // 0..3
    int chunk = blockIdx.y;                       // 0..147
    int tid   = threadIdx.x;
    int wid   = tid >> 5;
    int lane  = tid & 31;
    int r0    = slice * 128;

    for (int idx = tid; idx < INP_DIM * 128; idx += 256) {
        int i = idx >> 7, rr = idx & 127;
        w_sh[idx] = g_winpT[(size_t)i * N_REC + r0 + rr];
    }
    __syncthreads();

    int rowbase = chunk * ROWS_PER_CTA;
    int row0 = rowbase + wid;
    unsigned mw = (lane < 8) ? __ldg(&g_masks[(size_t)row0 * 8 + lane]) : 0u;

    for (int j = 0; j < ROWS_PER_CTA / 8; j++) {
        int row = rowbase + j * 8 + wid;
        unsigned curw = mw;
        if (j < ROWS_PER_CTA / 8 - 1)
            mw = (lane < 8) ? __ldg(&g_masks[(size_t)(row + 8) * 8 + lane]) : 0u;

        float4 acc = make_float4(0.f, 0.f, 0.f, 0.f);
#pragma unroll
        for (int w = 0; w < 8; w++) {
            unsigned m = __shfl_sync(0xffffffffu, curw, w);
            int ibase = w * 32;
            while (m) {
                int i = ibase + __ffs((int)m) - 1;
                m &= (m - 1);
                float4 wv = *(const float4*)&w_sh[(i << 7) + (lane << 2)];
                acc.x += wv.x; acc.y += wv.y; acc.z += wv.z; acc.w += wv.w;
            }
        }
        int t = row >> 7, bb = row & 127;         // row = t*128 + b
        float4* dst = (float4*)(g_inp + ((size_t)bb * N_STEPS + t) * N_REC + r0) + lane;
        *dst = acc;
    }
}

// ---------------------------------------------------------------------------
// Kernel 4: per-step scan fed from cp.async double-buffered smem windows.
//   1 CTA/batch, 512 threads (1 neuron/thread). One __syncthreads per step.
//   Dynamic smem: 2 x 32 KB input windows.
// ---------------------------------------------------------------------------
#define K_SCAN_SMEM (2 * WSTEPS * N_REC * 4)     // 65536 bytes

__device__ __forceinline__ float gather_rec(const unsigned* mask, int r) {
    float acc = 0.f;
#pragma unroll 4
    for (int wd = 0; wd < 16; wd++) {
        unsigned m = mask[wd];
        while (m) {
            int l = __ffs((int)m) - 1;
            m &= (m - 1);
            int s = (wd << 5) + l;
            acc += g_wrecT[((size_t)s << 9) + r];
        }
    }
    return acc;
}

__device__ __forceinline__ float gather_out(const unsigned* mask, int o) {
    float acc = 0.f;
#pragma unroll 4
    for (int wd = 0; wd < 16; wd++) {
        unsigned m = mask[wd];
        while (m) {
            int l = __ffs((int)m) - 1;
            m &= (m - 1);
            int s = (wd << 5) + l;
            acc += g_woutT[(s << 5) + o];
        }
    }
    return acc;
}

__global__ void __launch_bounds__(512) k_scan(float* __restrict__ out) {
    extern __shared__ float sbuf[];                        // 2 x WSTEPS*N_REC
    __shared__ __align__(16) unsigned smask[2][16];        // spike masks, ping-pong

    int b    = blockIdx.x;
    int tid  = threadIdx.x;
    int wid  = tid >> 5;
    int lane = tid & 31;

    const float* gbase = g_inp + (size_t)b * N_STEPS * N_REC;

    auto issue_copy = [&](int w, int buf) {
        const float* src = gbase + (size_t)w * WSTEPS * N_REC + tid * 4;
        unsigned dst = (unsigned)__cvta_generic_to_shared(
            &sbuf[buf * (WSTEPS * N_REC) + tid * 4]);
#pragma unroll
        for (int j = 0; j < 4; j++)
            asm volatile("cp.async.cg.shared.global [%0], [%1], 16;" ::
                         "r"(dst + j * 8192), "l"(src + j * 2048) : "memory");
        asm volatile("cp.async.commit_group;" ::: "memory");
    };

    if (tid < OUT_DIM) out[b * OUT_DIM + tid] = 0.f;       // out[0] = 0

    issue_copy(0, 0);
    issue_copy(1, 1);

    float v = 0.f, zprev = 0.f, vo = 0.f;
    int any_prev = 0, pm = 0;

    for (int w = 0; w < NWIN; w++) {
        int t0 = w * WSTEPS;
        int C = N_STEPS - t0; if (C > WSTEPS) C = WSTEPS;

        asm volatile("cp.async.wait_group 1;" ::: "memory");
        __syncthreads();                                   // window w resident
        const float* sb = sbuf + (w & 1) * (WSTEPS * N_REC);

        for (int c = 0; c < C; c++) {
            // 1. membrane update (prev-step spikes already visible in smask[pm])
            float vn = fmaf(ALPHA, v, sb[c * N_REC + tid]) - zprev * THR;
            if (any_prev) vn += gather_rec(smask[pm], tid);
            int z = vn > THR;
            v = vn;
            zprev = z ? 1.f : 0.f;

            // 2. publish this step's spikes (buffer pm^1: last read two steps ago)
            unsigned bal = __ballot_sync(0xffffffffu, z);
            int np = pm ^ 1;
            if (lane == 0) smask[np][wid] = bal;
            __syncthreads();                               // the one barrier/step

            // 3. block-wide any: 4 x LDS.128 broadcast + OR tree
            const uint4* m4 = (const uint4*)smask[np];
            uint4 q0 = m4[0], q1 = m4[1], q2 = m4[2], q3 = m4[3];
            unsigned any = (q0.x | q0.y | q0.z | q0.w) | (q1.x | q1.y | q1.z | q1.w)
                         | (q2.x | q2.y | q2.z | q2.w) | (q3.x | q3.y | q3.z | q3.w);

            // 4. output layer (warp 0): uses THIS step's spikes
            if (wid == 0) {
                float vacc = KAPPA * vo;
                if (any) vacc += gather_out(smask[np], lane);
                vo = vacc;
                out[(size_t)(t0 + c + 1) * (N_B * OUT_DIM) + b * OUT_DIM + lane] = vo;
            }
            any_prev = any != 0;
            pm = np;
        }

        __syncthreads();                 // all done reading sbuf[w&1]
        int wn = w + 2; if (wn > NWIN - 1) wn = NWIN - 1;   // clamp; pad covers tail
        issue_copy(wn, w & 1);
    }
    asm volatile("cp.async.wait_all;" ::: "memory");
}

// ---------------------------------------------------------------------------
extern "C" void kernel_launch(void* const* d_in, const int* in_sizes, int n_in,
                              void* d_out, int out_size) {
    const float* x     = (const float*)d_in[0];
    const float* w_inp = (const float*)d_in[1];
    const float* w_rec = (const float*)d_in[2];
    const float* w_out = (const float*)d_in[3];
    float* out = (float*)d_out;

    cudaFuncSetAttribute(k_inp_kernel,
                         cudaFuncAttributeMaxDynamicSharedMemorySize, K_INP_SMEM);
    cudaFuncSetAttribute(k_scan,
                         cudaFuncAttributeMaxDynamicSharedMemorySize, K_SCAN_SMEM);

    k_masks<<<dim3(N_B, 4), 256>>>(x);
    k_prep<<<256, 256>>>(w_rec, w_out, w_inp);
    k_inp_kernel<<<dim3(4, 148), 256, K_INP_SMEM>>>();
    k_scan<<<N_B, 512, K_SCAN_SMEM>>>(out);
}